// round 2
// baseline (speedup 1.0000x reference)
#include <cuda_runtime.h>
#include <cuda_bf16.h>
#include <cstdint>

// VACF via band-Gram on tensor cores.
// S[t] = sum_i x_i . x_{i+t}  (rows of flat [T, D]), out[t] = S[t]/((T-t)*D)
// Gram tiles (P,P) and (P,P+1) of 128 time-rows cover all lags 0..103.
// Precision: x = hi + lo (both bf16); C = hiA.hiB + loA.hiB + hiA.loB (3-pass).

#define T_DIM 10000
#define D_DIM 3000
#define DP    3008              // D padded to multiple of 32 (zero pad)
#define NTILE 79                // ceil(10000/128)
#define TPAD  (NTILE * 128)     // 10112
#define KC    32                // K elements per smem chunk
#define NCH   (DP / KC)         // 94
#define STR   40                // smem row stride (elements) -> conflict-free ldmatrix
#define TILE_ELE (128 * STR)    // 5120 elems = 10240 B per tile
#define W_MAX 100

__device__ __nv_bfloat16 g_hi[(size_t)TPAD * DP];   // ~60.8 MB
__device__ __nv_bfloat16 g_lo[(size_t)TPAD * DP];   // ~60.8 MB
__device__ double g_band[128];

// ---------------- conversion: f32 -> (hi, lo) bf16 split, zero-padded ----------------
__global__ void vacf_conv(const float* __restrict__ vel) {
    if (blockIdx.x == 0 && threadIdx.x < 128) g_band[threadIdx.x] = 0.0;
    long idx = (long)blockIdx.x * blockDim.x + threadIdx.x;   // vec4 index
    const long NV = (long)TPAD * (DP / 4);
    if (idx >= NV) return;
    int r  = (int)(idx / (DP / 4));
    int c4 = (int)(idx % (DP / 4));
    float4 v = make_float4(0.f, 0.f, 0.f, 0.f);
    if (r < T_DIM && c4 < (D_DIM / 4))
        v = *reinterpret_cast<const float4*>(vel + (size_t)r * D_DIM + c4 * 4);
    __nv_bfloat162 h01 = __float22bfloat162_rn(make_float2(v.x, v.y));
    __nv_bfloat162 h23 = __float22bfloat162_rn(make_float2(v.z, v.w));
    float l0 = v.x - __bfloat162float(h01.x);
    float l1 = v.y - __bfloat162float(h01.y);
    float l2 = v.z - __bfloat162float(h23.x);
    float l3 = v.w - __bfloat162float(h23.y);
    __nv_bfloat162 q01 = __float22bfloat162_rn(make_float2(l0, l1));
    __nv_bfloat162 q23 = __float22bfloat162_rn(make_float2(l2, l3));
    size_t off = (size_t)r * DP + c4 * 4;
    uint2 hh, ll;
    hh.x = *reinterpret_cast<unsigned*>(&h01); hh.y = *reinterpret_cast<unsigned*>(&h23);
    ll.x = *reinterpret_cast<unsigned*>(&q01); ll.y = *reinterpret_cast<unsigned*>(&q23);
    *reinterpret_cast<uint2*>(&g_hi[off]) = hh;
    *reinterpret_cast<uint2*>(&g_lo[off]) = ll;
}

// ---------------- Gram kernel ----------------
__device__ __forceinline__ void ldsm4(unsigned a, unsigned& r0, unsigned& r1,
                                      unsigned& r2, unsigned& r3) {
    asm volatile("ldmatrix.sync.aligned.m8n8.x4.shared.b16 {%0,%1,%2,%3}, [%4];"
                 : "=r"(r0), "=r"(r1), "=r"(r2), "=r"(r3) : "r"(a));
}

__device__ __forceinline__ void mma16816(float* c, const unsigned* a, const unsigned* b) {
    asm("mma.sync.aligned.m16n8k16.row.col.f32.bf16.bf16.f32 "
        "{%0,%1,%2,%3}, {%4,%5,%6,%7}, {%8,%9}, {%0,%1,%2,%3};"
        : "+f"(c[0]), "+f"(c[1]), "+f"(c[2]), "+f"(c[3])
        : "r"(a[0]), "r"(a[1]), "r"(a[2]), "r"(a[3]), "r"(b[0]), "r"(b[1]));
}

#define CPA16(dst, src) \
    asm volatile("cp.async.cg.shared.global [%0], [%1], 16;" :: "r"(dst), "l"(src))

__global__ __launch_bounds__(256, 2) void vacf_gram() {
    extern __shared__ __align__(128) __nv_bfloat16 sm[];
    __shared__ float s_band[W_MAX + 8];

    const int tid  = threadIdx.x;
    const int lane = tid & 31;
    const int warp = tid >> 5;

    const int bx  = blockIdx.x;
    const int pid = bx >> 1;
    const int kh  = bx & 1;
    const bool diag = (pid < NTILE);
    const int P = diag ? pid : pid - NTILE;
    const int Q = diag ? P : P + 1;

    const __nv_bfloat16* __restrict__ Ahig = g_hi + (size_t)P * 128 * DP;
    const __nv_bfloat16* __restrict__ Alog = g_lo + (size_t)P * 128 * DP;
    const __nv_bfloat16* __restrict__ Bhig = g_hi + (size_t)Q * 128 * DP;
    const __nv_bfloat16* __restrict__ Blog = g_lo + (size_t)Q * 128 * DP;

    const unsigned smu = (unsigned)__cvta_generic_to_shared(sm);

    if (tid < W_MAX + 8) s_band[tid] = 0.f;

    // warp tile: 32 (M) x 64 (N)
    const int wm = warp >> 1;          // 0..3
    const int wn = warp & 1;           // 0..1
    const int m0 = wm * 32;
    const int n0 = wn * 64;
    const int rl = lane & 7, gg = lane >> 3;

    float c[2][8][4];
    #pragma unroll
    for (int a = 0; a < 2; a++)
        #pragma unroll
        for (int b = 0; b < 8; b++)
            #pragma unroll
            for (int q = 0; q < 4; q++) c[a][b][q] = 0.f;

    const int cbeg = kh ? (NCH / 2) : 0;
    const int cend = kh ? NCH : (NCH / 2);

    auto load_tiles = [&](int st, int ci) {
        const int k0 = ci * KC;
        #pragma unroll
        for (int t2 = 0; t2 < 2; t2++) {
            int sid = tid + (t2 << 8);          // 0..511
            int row = sid >> 2;
            int seg = sid & 3;
            size_t goff  = (size_t)row * DP + k0 + seg * 8;
            unsigned soff = (unsigned)((row * STR + seg * 8) * 2);
            unsigned sb = smu + (unsigned)(st * 4) * (TILE_ELE * 2);
            CPA16(sb + 0 * (TILE_ELE * 2) + soff, Ahig + goff);
            CPA16(sb + 1 * (TILE_ELE * 2) + soff, Alog + goff);
            if (!diag) {
                CPA16(sb + 2 * (TILE_ELE * 2) + soff, Bhig + goff);
                CPA16(sb + 3 * (TILE_ELE * 2) + soff, Blog + goff);
            }
        }
        asm volatile("cp.async.commit_group;" ::: "memory");
    };

    load_tiles(0, cbeg);

    for (int ci = cbeg; ci < cend; ci++) {
        const int st = (ci - cbeg) & 1;
        if (ci + 1 < cend) {
            load_tiles(st ^ 1, ci + 1);
            asm volatile("cp.async.wait_group 1;" ::: "memory");
        } else {
            asm volatile("cp.async.wait_group 0;" ::: "memory");
        }
        __syncthreads();

        const unsigned baseAhi = smu + (unsigned)(st * 4 + 0) * (TILE_ELE * 2);
        const unsigned baseAlo = smu + (unsigned)(st * 4 + 1) * (TILE_ELE * 2);
        const unsigned baseBhi = smu + (unsigned)(st * 4 + (diag ? 0 : 2)) * (TILE_ELE * 2);
        const unsigned baseBlo = smu + (unsigned)(st * 4 + (diag ? 1 : 3)) * (TILE_ELE * 2);

        #pragma unroll
        for (int ks = 0; ks < 2; ks++) {
            const int kk = ks * 16;
            const int arow = rl + ((gg & 1) << 3);
            const int acol = kk + ((gg >> 1) << 3);
            unsigned ahi[2][4], alo[2][4];
            #pragma unroll
            for (int mi = 0; mi < 2; mi++) {
                unsigned aoff = (unsigned)(((m0 + mi * 16 + arow) * STR + acol) * 2);
                ldsm4(baseAhi + aoff, ahi[mi][0], ahi[mi][1], ahi[mi][2], ahi[mi][3]);
                ldsm4(baseAlo + aoff, alo[mi][0], alo[mi][1], alo[mi][2], alo[mi][3]);
            }
            const int brow = rl + ((gg >> 1) << 3);
            const int bcol = kk + ((gg & 1) << 3);
            #pragma unroll
            for (int njp = 0; njp < 4; njp++) {
                unsigned boff = (unsigned)(((n0 + njp * 16 + brow) * STR + bcol) * 2);
                unsigned bhi[4], blo[4];
                ldsm4(baseBhi + boff, bhi[0], bhi[1], bhi[2], bhi[3]);
                ldsm4(baseBlo + boff, blo[0], blo[1], blo[2], blo[3]);
                #pragma unroll
                for (int mi = 0; mi < 2; mi++) {
                    #pragma unroll
                    for (int j = 0; j < 2; j++) {
                        const int nj = njp * 2 + j;
                        mma16816(c[mi][nj], ahi[mi], &bhi[j * 2]);
                        mma16816(c[mi][nj], alo[mi], &bhi[j * 2]);
                        mma16816(c[mi][nj], ahi[mi], &blo[j * 2]);
                    }
                }
            }
        }
        __syncthreads();
    }

    // ---- band extraction ----
    #pragma unroll
    for (int mi = 0; mi < 2; mi++)
        #pragma unroll
        for (int nj = 0; nj < 8; nj++)
            #pragma unroll
            for (int q = 0; q < 4; q++) {
                int r  = m0 + mi * 16 + (lane >> 2) + ((q >> 1) << 3);
                int cc = n0 + nj * 8 + ((lane & 3) << 1) + (q & 1);
                int d  = cc - r;
                int t  = diag ? d : 128 + d;
                if (t >= 0 && t < W_MAX)
                    atomicAdd(&s_band[t], c[mi][nj][q]);
            }
    __syncthreads();
    if (tid < W_MAX) atomicAdd(&g_band[tid], (double)s_band[tid]);
}

// ---------------- finalize ----------------
__global__ void vacf_fin(float* __restrict__ out, int W) {
    int t = threadIdx.x;
    if (t < W)
        out[t] = (float)(g_band[t] / ((double)(T_DIM - t) * (double)D_DIM));
}

extern "C" void kernel_launch(void* const* d_in, const int* in_sizes, int n_in,
                              void* d_out, int out_size) {
    const float* vel = (const float*)d_in[0];

    size_t sh = (size_t)8 * TILE_ELE * sizeof(__nv_bfloat16);   // 81920 B
    cudaFuncSetAttribute(vacf_gram, cudaFuncAttributeMaxDynamicSharedMemorySize, (int)sh);

    long nv = (long)TPAD * (DP / 4);
    int cblocks = (int)((nv + 255) / 256);
    vacf_conv<<<cblocks, 256>>>(vel);

    vacf_gram<<<2 * (2 * NTILE - 1), 256, sh>>>();   // 314 CTAs

    vacf_fin<<<1, 128>>>((float*)d_out, out_size);
}

// round 4
// speedup vs baseline: 1.3204x; 1.3204x over previous
#include <cuda_runtime.h>
#include <cuda_bf16.h>
#include <cstdint>

// VACF via band-Gram, parallelogram tiling on mma.sync bf16 (sm_103 base ISA).
// S[t] = sum_i x_i . x_{i+t}, x = hi + lo (bf16 split), 3 passes hh+hl+lh.
// Each CTA: A rows [i0, i0+128); warp w owns 16-row strip, computes cols
// [i0+16w, i0+16w+120) -> every (i, i+t), 0<=t<=99, exactly once.

#define T_DIM 10000
#define D_DIM 3000
#define DP    3008              // padded K (elements)
#define NTILE 79                // row tiles of 128
#define TPAD2 10240             // padded rows (covers 240-row halo)
#define KS    4                 // K splits
#define NCHT  94                // total K chunks of 32 elems
#define W_MAX 100
#define RB    240               // rows loaded per CTA (128 + halo, padded)
#define STRB  80                // smem row stride bytes (conflict-free ldsm)
#define TILE_B  (RB * STRB)     // 19200
#define STAGE_B (2 * TILE_B)    // hi + lo
#define SMEM_B  (2 * STAGE_B)   // double buffer: 76800

__device__ __nv_bfloat16 g_hi[(size_t)TPAD2 * DP];
__device__ __nv_bfloat16 g_lo[(size_t)TPAD2 * DP];
__device__ double g_band[128];

// ---------------- conversion: f32 -> (hi, lo) bf16 split, zero-padded ----------------
__global__ void vacf_conv(const float* __restrict__ vel) {
    if (blockIdx.x == 0 && threadIdx.x < 128) g_band[threadIdx.x] = 0.0;
    long idx = (long)blockIdx.x * blockDim.x + threadIdx.x;   // vec4 index
    const long NV = (long)TPAD2 * (DP / 4);
    if (idx >= NV) return;
    int r  = (int)(idx / (DP / 4));
    int c4 = (int)(idx % (DP / 4));
    float4 v = make_float4(0.f, 0.f, 0.f, 0.f);
    if (r < T_DIM && c4 < (D_DIM / 4))
        v = *reinterpret_cast<const float4*>(vel + (size_t)r * D_DIM + c4 * 4);
    __nv_bfloat162 h01 = __float22bfloat162_rn(make_float2(v.x, v.y));
    __nv_bfloat162 h23 = __float22bfloat162_rn(make_float2(v.z, v.w));
    float l0 = v.x - __bfloat162float(h01.x);
    float l1 = v.y - __bfloat162float(h01.y);
    float l2 = v.z - __bfloat162float(h23.x);
    float l3 = v.w - __bfloat162float(h23.y);
    __nv_bfloat162 q01 = __float22bfloat162_rn(make_float2(l0, l1));
    __nv_bfloat162 q23 = __float22bfloat162_rn(make_float2(l2, l3));
    size_t off = (size_t)r * DP + c4 * 4;
    uint2 hh, ll;
    hh.x = *reinterpret_cast<unsigned*>(&h01); hh.y = *reinterpret_cast<unsigned*>(&h23);
    ll.x = *reinterpret_cast<unsigned*>(&q01); ll.y = *reinterpret_cast<unsigned*>(&q23);
    *reinterpret_cast<uint2*>(&g_hi[off]) = hh;
    *reinterpret_cast<uint2*>(&g_lo[off]) = ll;
}

// ---------------- Gram kernel ----------------
__device__ __forceinline__ void ldsm4(unsigned a, unsigned& r0, unsigned& r1,
                                      unsigned& r2, unsigned& r3) {
    asm volatile("ldmatrix.sync.aligned.m8n8.x4.shared.b16 {%0,%1,%2,%3}, [%4];"
                 : "=r"(r0), "=r"(r1), "=r"(r2), "=r"(r3) : "r"(a));
}

__device__ __forceinline__ void mma16816(float* c, const unsigned* a, const unsigned* b) {
    asm("mma.sync.aligned.m16n8k16.row.col.f32.bf16.bf16.f32 "
        "{%0,%1,%2,%3}, {%4,%5,%6,%7}, {%8,%9}, {%0,%1,%2,%3};"
        : "+f"(c[0]), "+f"(c[1]), "+f"(c[2]), "+f"(c[3])
        : "r"(a[0]), "r"(a[1]), "r"(a[2]), "r"(a[3]), "r"(b[0]), "r"(b[1]));
}

#define CPA16(dst, src) \
    asm volatile("cp.async.cg.shared.global [%0], [%1], 16;" :: "r"(dst), "l"(src))

__global__ __launch_bounds__(256, 2) void vacf_gram() {
    extern __shared__ __align__(128) char sm[];
    __shared__ float s_band[W_MAX];

    const int tid  = threadIdx.x;
    const int warp = tid >> 5;
    const int lane = tid & 31;

    const int s  = blockIdx.x / NTILE;      // K-split index
    const int P  = blockIdx.x % NTILE;
    const int i0 = P * 128;

    const int c0 = (s * NCHT) / KS;
    const int c1 = ((s + 1) * NCHT) / KS;

    const __nv_bfloat16* gb[2] = { g_hi + (size_t)i0 * DP, g_lo + (size_t)i0 * DP };

    const unsigned smu = (unsigned)__cvta_generic_to_shared(sm);

    if (tid < W_MAX) s_band[tid] = 0.f;

    auto load_chunk = [&](int ci, int st) {
        const int k0 = ci * 32;             // element offset along K
        #pragma unroll
        for (int k = 0; k < 8; k++) {
            int sid = tid + (k << 8);       // 0..2047, use < 1920
            if (sid < 2 * RB * 4) {
                int hl  = sid >= RB * 4;        // 0 = hi, 1 = lo
                int rs  = sid - hl * (RB * 4);
                int row = rs >> 2;
                int seg = rs & 3;
                const __nv_bfloat16* gp = gb[hl] + (size_t)row * DP + k0 + seg * 8;
                unsigned so = smu + st * STAGE_B + hl * TILE_B + row * STRB + seg * 16;
                CPA16(so, gp);
            }
        }
        asm volatile("cp.async.commit_group;" ::: "memory");
    };

    // accumulators: 15 n-tiles x 4
    float c[15][4];
    #pragma unroll
    for (int i = 0; i < 15; i++)
        #pragma unroll
        for (int q = 0; q < 4; q++) c[i][q] = 0.f;

    const int rl = lane & 7, gg = lane >> 3;
    const int arow = 16 * warp + rl + ((gg & 1) << 3);
    const int acol0 = (gg >> 1) << 3;
    const int brow0 = 16 * warp + rl + ((gg >> 1) << 3);
    const int bcol0 = (gg & 1) << 3;

    load_chunk(c0, 0);

    for (int ci = c0; ci < c1; ci++) {
        const int st = (ci - c0) & 1;
        if (ci + 1 < c1) {
            load_chunk(ci + 1, st ^ 1);
            asm volatile("cp.async.wait_group 1;" ::: "memory");
        } else {
            asm volatile("cp.async.wait_group 0;" ::: "memory");
        }
        __syncthreads();

        const unsigned bhi_base = smu + st * STAGE_B;
        const unsigned blo_base = bhi_base + TILE_B;

        #pragma unroll
        for (int ks = 0; ks < 2; ks++) {
            const int kk = ks * 16;
            // A fragments (rows 16w..16w+15), hi and lo
            unsigned ahi[4], alo[4];
            {
                unsigned aoff = (unsigned)(arow * STRB + (kk + acol0) * 2);
                ldsm4(bhi_base + aoff, ahi[0], ahi[1], ahi[2], ahi[3]);
                ldsm4(blo_base + aoff, alo[0], alo[1], alo[2], alo[3]);
            }
            #pragma unroll
            for (int njp = 0; njp < 8; njp++) {
                unsigned boff = (unsigned)((brow0 + njp * 16) * STRB + (kk + bcol0) * 2);
                unsigned bhi[4], blo[4];
                ldsm4(bhi_base + boff, bhi[0], bhi[1], bhi[2], bhi[3]);
                ldsm4(blo_base + boff, blo[0], blo[1], blo[2], blo[3]);
                #pragma unroll
                for (int j = 0; j < 2; j++) {
                    const int nj = njp * 2 + j;
                    if (nj < 15) {
                        mma16816(c[nj], ahi, &bhi[j * 2]);   // hh
                        mma16816(c[nj], ahi, &blo[j * 2]);   // hl
                        mma16816(c[nj], alo, &bhi[j * 2]);   // lh
                    }
                }
            }
        }
        __syncthreads();
    }

    // ---- band extraction: t independent of warp/tile base ----
    #pragma unroll
    for (int nj = 0; nj < 15; nj++)
        #pragma unroll
        for (int q = 0; q < 4; q++) {
            int t = nj * 8 + ((lane & 3) << 1) + (q & 1)
                  - (lane >> 2) - ((q >> 1) << 3);
            if (t >= 0 && t < W_MAX) atomicAdd(&s_band[t], c[nj][q]);
        }
    __syncthreads();
    if (tid < W_MAX) atomicAdd(&g_band[tid], (double)s_band[tid]);
}

// ---------------- finalize ----------------
__global__ void vacf_fin(float* __restrict__ out, int W) {
    int t = threadIdx.x;
    if (t < W)
        out[t] = (float)(g_band[t] / ((double)(T_DIM - t) * (double)D_DIM));
}

extern "C" void kernel_launch(void* const* d_in, const int* in_sizes, int n_in,
                              void* d_out, int out_size) {
    const float* vel = (const float*)d_in[0];

    cudaFuncSetAttribute(vacf_gram, cudaFuncAttributeMaxDynamicSharedMemorySize, SMEM_B);

    long nv = (long)TPAD2 * (DP / 4);
    int cblocks = (int)((nv + 255) / 256);
    vacf_conv<<<cblocks, 256>>>(vel);

    vacf_gram<<<NTILE * KS, 256, SMEM_B>>>();

    vacf_fin<<<1, 128>>>((float*)d_out, out_size);
}

// round 5
// speedup vs baseline: 1.9028x; 1.4411x over previous
#include <cuda_runtime.h>
#include <cuda_bf16.h>
#include <cstdint>

// VACF via band-Gram, parallelogram tiling on mma.sync bf16, fused f32->bf16
// split conversion, chunk-balanced persistent grid (296 CTAs = 2/SM x 148).
// S[t] = sum_i x_i . x_{i+t}; x = hi + lo (bf16); 3 passes hh+hl+lh.
// Tile P: A rows [128P, 128P+128); warp w computes cols [128P+16w, +120).

#define T_DIM 10000
#define D_DIM 3000
#define NTILE 79                 // row tiles of 128
#define NCHT  94                 // K chunks of 32 elems (94*32 = 3008 >= 3000)
#define UNITS (NTILE * NCHT)     // 7426 chunk-units
#define NCTA  296
#define W_MAX 100
#define RB    240                // rows per tile (128 + halo)
#define F32_B   (RB * 128)       // f32 staging: 240 rows x 128 B = 30720
#define STRB    80               // bf16 smem row stride (conflict-free ldsm)
#define HTILE_B (RB * STRB)      // 19200
#define STAGE_B (2 * HTILE_B)    // hi + lo
#define SMEM_B  (F32_B + 2 * STAGE_B)   // 107520

__device__ double g_band[128];   // static zero-init; fin re-zeroes after read

// ---------------- helpers ----------------
__device__ __forceinline__ void ldsm4(unsigned a, unsigned& r0, unsigned& r1,
                                      unsigned& r2, unsigned& r3) {
    asm volatile("ldmatrix.sync.aligned.m8n8.x4.shared.b16 {%0,%1,%2,%3}, [%4];"
                 : "=r"(r0), "=r"(r1), "=r"(r2), "=r"(r3) : "r"(a));
}

__device__ __forceinline__ void mma16816(float* c, const unsigned* a, const unsigned* b) {
    asm("mma.sync.aligned.m16n8k16.row.col.f32.bf16.bf16.f32 "
        "{%0,%1,%2,%3}, {%4,%5,%6,%7}, {%8,%9}, {%0,%1,%2,%3};"
        : "+f"(c[0]), "+f"(c[1]), "+f"(c[2]), "+f"(c[3])
        : "r"(a[0]), "r"(a[1]), "r"(a[2]), "r"(a[3]), "r"(b[0]), "r"(b[1]));
}

// cp.async with src-size arg: z = 16 (copy) or 0 (zero-fill)
#define CPA16Z(dst, src, z) \
    asm volatile("cp.async.cg.shared.global [%0], [%1], 16, %2;" \
                 :: "r"(dst), "l"(src), "r"(z))

__global__ __launch_bounds__(256, 2) void vacf_gram(const float* __restrict__ vel) {
    extern __shared__ __align__(128) char sm[];
    __shared__ float s_band[W_MAX];

    const int tid  = threadIdx.x;
    const int warp = tid >> 5;
    const int lane = tid & 31;
    const int g    = blockIdx.x;

    const unsigned smu  = (unsigned)__cvta_generic_to_shared(sm);
    const unsigned f32b = smu;                 // f32 staging
    const unsigned bf0  = smu + F32_B;         // bf16 stages

    if (tid < W_MAX) s_band[tid] = 0.f;

    // fragment-layout constants (validated in R4)
    const int rl = lane & 7, gg = lane >> 3;
    const int arow  = 16 * warp + rl + ((gg & 1) << 3);
    const int acol0 = (gg >> 1) << 3;
    const int brow0 = 16 * warp + rl + ((gg >> 1) << 3);
    const int bcol0 = (gg & 1) << 3;

    // this thread's load/convert slots (7.5 avg -> 8 rounds, guard sid<1920)
    // sid -> row = sid>>3, seg = sid&7   (seg = 4-elem group)

    // global chunk-unit range for this CTA
    int u  = (int)(((long)g * UNITS) / NCTA);
    const int u1 = (int)(((long)(g + 1) * UNITS) / NCTA);

    float c[15][4];

    while (u < u1) {
        const int tile = u / NCHT;
        const int cbeg = u % NCHT;
        const int cend = (cbeg + (u1 - u) < NCHT) ? cbeg + (u1 - u) : NCHT;
        const int R0   = tile * 128;
        u += cend - cbeg;

        #pragma unroll
        for (int i = 0; i < 15; i++)
            #pragma unroll
            for (int q = 0; q < 4; q++) c[i][q] = 0.f;

        // issue f32 loads for a chunk into the staging buffer
        auto load_f32 = [&](int ci) {
            #pragma unroll
            for (int k = 0; k < 8; k++) {
                int sid = tid + (k << 8);
                if (sid < RB * 8) {
                    int row = sid >> 3;
                    int seg = sid & 7;
                    int gr  = R0 + row;
                    int c4  = ci * 8 + seg;
                    unsigned ok = (gr < T_DIM && c4 < (D_DIM / 4)) ? 16u : 0u;
                    const float* gp = vel + ((size_t)(gr < T_DIM ? gr : 0)) * D_DIM
                                          + (c4 < (D_DIM / 4) ? c4 : 0) * 4;
                    CPA16Z(f32b + (unsigned)(row * 128 + seg * 16), gp, ok);
                }
            }
            asm volatile("cp.async.commit_group;" ::: "memory");
        };

        load_f32(cbeg);

        for (int ci = cbeg; ci < cend; ci++) {
            const int st = (ci - cbeg) & 1;
            asm volatile("cp.async.wait_group 0;" ::: "memory");
            __syncthreads();                       // f32 chunk ci ready; prior compute done

            // convert f32 staging -> bf16 hi/lo stage st
            const unsigned hib = bf0 + st * STAGE_B;
            const unsigned lob = hib + HTILE_B;
            #pragma unroll
            for (int k = 0; k < 8; k++) {
                int sid = tid + (k << 8);
                if (sid < RB * 8) {
                    int row = sid >> 3;
                    int seg = sid & 7;
                    const float4 v = *reinterpret_cast<const float4*>(
                        sm + (row * 128 + seg * 16));
                    __nv_bfloat162 h01 = __float22bfloat162_rn(make_float2(v.x, v.y));
                    __nv_bfloat162 h23 = __float22bfloat162_rn(make_float2(v.z, v.w));
                    float l0 = v.x - __bfloat162float(h01.x);
                    float l1 = v.y - __bfloat162float(h01.y);
                    float l2 = v.z - __bfloat162float(h23.x);
                    float l3 = v.w - __bfloat162float(h23.y);
                    __nv_bfloat162 q01 = __float22bfloat162_rn(make_float2(l0, l1));
                    __nv_bfloat162 q23 = __float22bfloat162_rn(make_float2(l2, l3));
                    uint2 hh, ll;
                    hh.x = *reinterpret_cast<unsigned*>(&h01);
                    hh.y = *reinterpret_cast<unsigned*>(&h23);
                    ll.x = *reinterpret_cast<unsigned*>(&q01);
                    ll.y = *reinterpret_cast<unsigned*>(&q23);
                    unsigned off = (unsigned)(row * STRB + seg * 8);
                    *reinterpret_cast<uint2*>(sm + (F32_B + st * STAGE_B) + off) = hh;
                    *reinterpret_cast<uint2*>(sm + (F32_B + st * STAGE_B + HTILE_B) + off) = ll;
                }
            }
            __syncthreads();                       // conversion visible; staging consumed

            if (ci + 1 < cend) load_f32(ci + 1);   // overlap with compute

            // compute stage st
            #pragma unroll
            for (int ks = 0; ks < 2; ks++) {
                const int kk = ks * 16;
                unsigned ahi[4], alo[4];
                {
                    unsigned aoff = (unsigned)(arow * STRB + (kk + acol0) * 2);
                    ldsm4(hib + aoff, ahi[0], ahi[1], ahi[2], ahi[3]);
                    ldsm4(lob + aoff, alo[0], alo[1], alo[2], alo[3]);
                }
                #pragma unroll
                for (int njp = 0; njp < 8; njp++) {
                    unsigned boff = (unsigned)((brow0 + njp * 16) * STRB + (kk + bcol0) * 2);
                    unsigned bhi[4], blo[4];
                    ldsm4(hib + boff, bhi[0], bhi[1], bhi[2], bhi[3]);
                    ldsm4(lob + boff, blo[0], blo[1], blo[2], blo[3]);
                    const int nj0 = njp * 2;
                    // interleaved passes: same-accumulator distance = 2
                    mma16816(c[nj0], ahi, &bhi[0]);
                    if (nj0 + 1 < 15) mma16816(c[nj0 + 1], ahi, &bhi[2]);
                    mma16816(c[nj0], ahi, &blo[0]);
                    if (nj0 + 1 < 15) mma16816(c[nj0 + 1], ahi, &blo[2]);
                    mma16816(c[nj0], alo, &bhi[0]);
                    if (nj0 + 1 < 15) mma16816(c[nj0 + 1], alo, &bhi[2]);
                }
            }
        }

        // ---- segment epilogue: band extraction ----
        __syncthreads();   // ensure s_band from previous segment flushed/zeroed
        #pragma unroll
        for (int nj = 0; nj < 15; nj++)
            #pragma unroll
            for (int q = 0; q < 4; q++) {
                int t = nj * 8 + ((lane & 3) << 1) + (q & 1)
                      - (lane >> 2) - ((q >> 1) << 3);
                if (t >= 0 && t < W_MAX) atomicAdd(&s_band[t], c[nj][q]);
            }
        __syncthreads();
        if (tid < W_MAX) {
            atomicAdd(&g_band[tid], (double)s_band[tid]);
            s_band[tid] = 0.f;
        }
    }
}

// ---------------- finalize (+ re-zero g_band for next graph replay) ----------------
__global__ void vacf_fin(float* __restrict__ out, int W) {
    int t = threadIdx.x;
    if (t < W)
        out[t] = (float)(g_band[t] / ((double)(T_DIM - t) * (double)D_DIM));
    if (t < 128) g_band[t] = 0.0;
}

extern "C" void kernel_launch(void* const* d_in, const int* in_sizes, int n_in,
                              void* d_out, int out_size) {
    const float* vel = (const float*)d_in[0];

    cudaFuncSetAttribute(vacf_gram, cudaFuncAttributeMaxDynamicSharedMemorySize, SMEM_B);
    vacf_gram<<<NCTA, 256, SMEM_B>>>(vel);
    vacf_fin<<<1, 128>>>((float*)d_out, out_size);
}